// round 2
// baseline (speedup 1.0000x reference)
#include <cuda_runtime.h>
#include <mma.h>
#include <math.h>

using namespace nvcuda;

#define BATCH  8
#define SEQ    4096
#define DIM    1024
#define SDIM   64
#define SHIFTN 2048
#define MTOT   (BATCH*SEQ)   /* 32768 */
#define CH     512
#define NCH    (SEQ/CH)      /* 8 */

#define SLD 20   /* smem leading dim for 16-wide K chunks (+4 pad) */

// Scratch
__device__ float g_xs[(size_t)MTOT * DIM];
__device__ float g_k[(size_t)MTOT * SDIM];
__device__ float g_v[(size_t)MTOT * SDIM];
__device__ float g_wkv[(size_t)MTOT * SDIM];
__device__ float g_states[(size_t)MTOT * SDIM];
__device__ float g_lasts[BATCH * NCH * SDIM];
__device__ float g_carry[BATCH * NCH * SDIM];

__device__ __forceinline__ float to_tf32(float v) {
    float r; asm("cvt.rna.tf32.f32 %0, %1;" : "=f"(r) : "f"(v)); return r;
}

__device__ __forceinline__ void split_store(float* H, float* L, int off, float4 v) {
    float h0 = to_tf32(v.x), h1 = to_tf32(v.y), h2 = to_tf32(v.z), h3 = to_tf32(v.w);
    H[off+0] = h0; H[off+1] = h1; H[off+2] = h2; H[off+3] = h3;
    L[off+0] = to_tf32(v.x - h0);
    L[off+1] = to_tf32(v.y - h1);
    L[off+2] = to_tf32(v.z - h2);
    L[off+3] = to_tf32(v.w - h3);
}

typedef wmma::fragment<wmma::matrix_a, 16, 16, 8, wmma::precision::tf32, wmma::row_major> FragA;
typedef wmma::fragment<wmma::matrix_b, 16, 16, 8, wmma::precision::tf32, wmma::col_major> FragB;
typedef wmma::fragment<wmma::accumulator, 16, 16, 8, float> FragC;

// 3xTF32 mma over one 16-wide K chunk held in smem (hi/lo for A and B).
// Warp computes a 64x32 sub-tile: 4 (m) x 2 (n) wmma tiles.
__device__ __forceinline__ void mma_on_chunk(const float* Ah, const float* Al,
                                             const float* Bh, const float* Bl,
                                             int wm, int wn, FragC c[4][2])
{
#pragma unroll
    for (int ks = 0; ks < 16; ks += 8) {
        FragB bh[2], bl[2];
#pragma unroll
        for (int j = 0; j < 2; j++) {
            wmma::load_matrix_sync(bh[j], Bh + (wn + j*16)*SLD + ks, SLD);
            wmma::load_matrix_sync(bl[j], Bl + (wn + j*16)*SLD + ks, SLD);
        }
        FragA ah[4];
#pragma unroll
        for (int i = 0; i < 4; i++)
            wmma::load_matrix_sync(ah[i], Ah + (wm + i*16)*SLD + ks, SLD);
#pragma unroll
        for (int i = 0; i < 4; i++)
#pragma unroll
            for (int j = 0; j < 2; j++)
                wmma::mma_sync(c[i][j], ah[i], bh[j], c[i][j]);
#pragma unroll
        for (int i = 0; i < 4; i++)
#pragma unroll
            for (int j = 0; j < 2; j++)
                wmma::mma_sync(c[i][j], ah[i], bl[j], c[i][j]);
        FragA al[4];
#pragma unroll
        for (int i = 0; i < 4; i++)
            wmma::load_matrix_sync(al[i], Al + (wm + i*16)*SLD + ks, SLD);
#pragma unroll
        for (int i = 0; i < 4; i++)
#pragma unroll
            for (int j = 0; j < 2; j++)
                wmma::mma_sync(c[i][j], al[i], bh[j], c[i][j]);
    }
}

// ---------------------------------------------------------------------------
// Kernel 1: raw shift GEMM  g_xs[m,e] = x_cat[m,:] @ W_shift[e,:]
// (gated blend deferred to LN kernel)
// ---------------------------------------------------------------------------
__global__ __launch_bounds__(256)
void k_shift_gemm(const float* __restrict__ x, const float* __restrict__ Wsh)
{
    __shared__ float Ah[128*SLD], Al[128*SLD], Bh[128*SLD], Bl[128*SLD];
    const int tid = threadIdx.x;
    const int m0 = blockIdx.y * 128;
    const int e0 = blockIdx.x * 128;
    const int warp = tid >> 5;
    const int wm = (warp & 1) * 64;
    const int wn = (warp >> 1) * 32;

    const int row0 = tid >> 2;
    const int c40  = (tid & 3) * 4;

    // A rows use shifted token index
    int m_a0 = m0 + row0;
    int b0 = m_a0 >> 12, t0 = m_a0 & 4095;
    int ts0 = t0 + SHIFTN; if (ts0 >= SEQ) ts0 -= SEQ;
    int m_a1 = m0 + row0 + 64;
    int b1 = m_a1 >> 12, t1 = m_a1 & 4095;
    int ts1 = t1 + SHIFTN; if (ts1 >= SEQ) ts1 -= SEQ;

    const float* ap0 = x + (size_t)(b0*SEQ + ts0)*DIM + c40;
    const float* ap1 = x + (size_t)(b1*SEQ + ts1)*DIM + c40;
    const float* bp0 = Wsh + (size_t)(e0 + row0)*DIM + c40;
    const float* bp1 = Wsh + (size_t)(e0 + row0 + 64)*DIM + c40;

    FragC c[4][2];
#pragma unroll
    for (int i = 0; i < 4; i++)
#pragma unroll
        for (int j = 0; j < 2; j++) wmma::fill_fragment(c[i][j], 0.0f);

    float4 ra0 = *(const float4*)(ap0);
    float4 ra1 = *(const float4*)(ap1);
    float4 rb0 = *(const float4*)(bp0);
    float4 rb1 = *(const float4*)(bp1);

    for (int k0 = 0; k0 < DIM; k0 += 16) {
        split_store(Ah, Al,  row0     *SLD + c40, ra0);
        split_store(Ah, Al, (row0+64) *SLD + c40, ra1);
        split_store(Bh, Bl,  row0     *SLD + c40, rb0);
        split_store(Bh, Bl, (row0+64) *SLD + c40, rb1);
        __syncthreads();
        int kn = (k0 + 16 < DIM) ? k0 + 16 : 0;
        ra0 = *(const float4*)(ap0 + kn);
        ra1 = *(const float4*)(ap1 + kn);
        rb0 = *(const float4*)(bp0 + kn);
        rb1 = *(const float4*)(bp1 + kn);
        mma_on_chunk(Ah, Al, Bh, Bl, wm, wn, c);
        __syncthreads();
    }

#pragma unroll
    for (int i = 0; i < 4; i++)
#pragma unroll
        for (int j = 0; j < 2; j++)
            wmma::store_matrix_sync(g_xs + (size_t)(m0 + wm + i*16)*DIM + (e0 + wn + j*16),
                                    c[i][j], DIM, wmma::mem_row_major);
}

// ---------------------------------------------------------------------------
// Kernel 2: blend + layernorm, in place on g_xs
// xs = raw*sigmoid(sg) + x*(1-sigmoid(sg)); then LN
// ---------------------------------------------------------------------------
__inline__ __device__ float warp_sum(float v) {
#pragma unroll
    for (int o = 16; o > 0; o >>= 1) v += __shfl_xor_sync(0xffffffffu, v, o);
    return v;
}

__global__ __launch_bounds__(256)
void k_ln(const float* __restrict__ x, const float* __restrict__ sg,
          const float* __restrict__ lnw, const float* __restrict__ lnb)
{
    int m = blockIdx.x;
    int tid = threadIdx.x;
    float4* row = (float4*)(g_xs + (size_t)m * DIM);
    float4 v  = row[tid];
    float4 xv = ((const float4*)(x + (size_t)m * DIM))[tid];
    float4 gv = ((const float4*)sg)[tid];
    float g0 = 1.f/(1.f+expf(-gv.x)), g1 = 1.f/(1.f+expf(-gv.y));
    float g2 = 1.f/(1.f+expf(-gv.z)), g3 = 1.f/(1.f+expf(-gv.w));
    v.x = v.x*g0 + xv.x*(1.f-g0);
    v.y = v.y*g1 + xv.y*(1.f-g1);
    v.z = v.z*g2 + xv.z*(1.f-g2);
    v.w = v.w*g3 + xv.w*(1.f-g3);

    float s  = v.x + v.y + v.z + v.w;
    float ss = fmaf(v.x, v.x, fmaf(v.y, v.y, fmaf(v.z, v.z, v.w * v.w)));
    s = warp_sum(s); ss = warp_sum(ss);
    __shared__ float sh_s[8], sh_ss[8];
    int wid = tid >> 5, lane = tid & 31;
    if (lane == 0) { sh_s[wid] = s; sh_ss[wid] = ss; }
    __syncthreads();
    if (wid == 0) {
        float a = (lane < 8) ? sh_s[lane] : 0.f;
        float b = (lane < 8) ? sh_ss[lane] : 0.f;
        a = warp_sum(a); b = warp_sum(b);
        if (lane == 0) { sh_s[0] = a; sh_ss[0] = b; }
    }
    __syncthreads();
    float mu  = sh_s[0] * (1.f / DIM);
    float var = sh_ss[0] * (1.f / DIM) - mu * mu;
    float rstd = rsqrtf(var + 1e-5f);
    float4 w4 = ((const float4*)lnw)[tid];
    float4 b4 = ((const float4*)lnb)[tid];
    v.x = (v.x - mu) * rstd * w4.x + b4.x;
    v.y = (v.y - mu) * rstd * w4.y + b4.y;
    v.z = (v.z - mu) * rstd * w4.z + b4.z;
    v.w = (v.w - mu) * rstd * w4.w + b4.w;
    row[tid] = v;
}

// ---------------------------------------------------------------------------
// Kernel 3: stacked k/v GEMM (N=128: cols 0..63 -> k, 64..127 -> v)
// ---------------------------------------------------------------------------
__global__ __launch_bounds__(256)
void k_kv_gemm(const float* __restrict__ Wk, const float* __restrict__ Wv)
{
    __shared__ float Ah[128*SLD], Al[128*SLD], Bh[128*SLD], Bl[128*SLD];
    const int tid = threadIdx.x;
    const int m0 = blockIdx.y * 128;
    const int warp = tid >> 5;
    const int wm = (warp & 1) * 64;
    const int wn = (warp >> 1) * 32;

    const int row0 = tid >> 2;
    const int c40  = (tid & 3) * 4;

    const float* ap0 = g_xs + (size_t)(m0 + row0)*DIM + c40;
    const float* ap1 = g_xs + (size_t)(m0 + row0 + 64)*DIM + c40;
    const float* bp0 = Wk + (size_t)row0 * DIM + c40;       // rows 0..63 -> Wk
    const float* bp1 = Wv + (size_t)row0 * DIM + c40;       // rows 64..127 -> Wv

    FragC c[4][2];
#pragma unroll
    for (int i = 0; i < 4; i++)
#pragma unroll
        for (int j = 0; j < 2; j++) wmma::fill_fragment(c[i][j], 0.0f);

    float4 ra0 = *(const float4*)(ap0);
    float4 ra1 = *(const float4*)(ap1);
    float4 rb0 = *(const float4*)(bp0);
    float4 rb1 = *(const float4*)(bp1);

    for (int k0 = 0; k0 < DIM; k0 += 16) {
        split_store(Ah, Al,  row0     *SLD + c40, ra0);
        split_store(Ah, Al, (row0+64) *SLD + c40, ra1);
        split_store(Bh, Bl,  row0     *SLD + c40, rb0);
        split_store(Bh, Bl, (row0+64) *SLD + c40, rb1);
        __syncthreads();
        int kn = (k0 + 16 < DIM) ? k0 + 16 : 0;
        ra0 = *(const float4*)(ap0 + kn);
        ra1 = *(const float4*)(ap1 + kn);
        rb0 = *(const float4*)(bp0 + kn);
        rb1 = *(const float4*)(bp1 + kn);
        mma_on_chunk(Ah, Al, Bh, Bl, wm, wn, c);
        __syncthreads();
    }

#pragma unroll
    for (int i = 0; i < 4; i++)
#pragma unroll
        for (int j = 0; j < 2; j++) {
            int cg = wn + j*16;
            float* dst = (cg < 64) ? (g_k + cg) : (g_v + (cg - 64));
            wmma::store_matrix_sync(dst + (size_t)(m0 + wm + i*16)*SDIM,
                                    c[i][j], SDIM, wmma::mem_row_major);
        }
}

// ---------------------------------------------------------------------------
// Kernel 4: wkv = exp(-exp(time_first[s]) * sigmoid(k)) * v
// ---------------------------------------------------------------------------
__global__ void k_wkv(const float* __restrict__ time_first)
{
    int i = blockIdx.x * blockDim.x + threadIdx.x;
    if (i >= MTOT * SDIM) return;
    int s = i & (SDIM - 1);
    float tf = expf(time_first[s]);
    float kk = g_k[i];
    float vv = g_v[i];
    float sig = 1.f / (1.f + expf(-kk));
    g_wkv[i] = expf(-tf * sig) * vv;
}

// ---------------------------------------------------------------------------
// Recurrence: chunked scan (3 kernels)
// ---------------------------------------------------------------------------
__global__ void k_rec_lasts(const float* __restrict__ td)
{
    int ch = blockIdx.x, b = blockIdx.y, s = threadIdx.x;
    float w = expf(td[s]);
    const float* wp = g_wkv + ((size_t)(b*SEQ + ch*CH))*SDIM + s;
    float st = 0.f;
#pragma unroll 8
    for (int t = 0; t < CH; t++) st = fmaf(st, w, wp[(size_t)t*SDIM]);
    g_lasts[(b*NCH + ch)*SDIM + s] = st;
}

__global__ void k_rec_carry(const float* __restrict__ td, float* __restrict__ last_out)
{
    int b = blockIdx.x, s = threadIdx.x;
    float wC = expf((float)CH * td[s]);   // w^CH
    float st = 0.f;
    for (int c = 0; c < NCH; c++) {
        g_carry[(b*NCH + c)*SDIM + s] = st;
        st = st*wC + g_lasts[(b*NCH + c)*SDIM + s];
    }
    last_out[b*SDIM + s] = st;
}

__global__ void k_rec_scan(const float* __restrict__ td)
{
    int ch = blockIdx.x, b = blockIdx.y, s = threadIdx.x;
    float w = expf(td[s]);
    float st = g_carry[(b*NCH + ch)*SDIM + s];
    const float* wp = g_wkv    + ((size_t)(b*SEQ + ch*CH))*SDIM + s;
    float*       sp = g_states + ((size_t)(b*SEQ + ch*CH))*SDIM + s;
#pragma unroll 8
    for (int t = 0; t < CH; t++) {
        st = fmaf(st, w, wp[(size_t)t*SDIM]);
        sp[(size_t)t*SDIM] = st;
    }
}

// ---------------------------------------------------------------------------
// Kernel 6: out[m,d] = sum_s states[m,s] * W_output[d,s]   (K=64, 3xTF32)
// ---------------------------------------------------------------------------
__global__ __launch_bounds__(256)
void k_out_gemm(const float* __restrict__ Wo, float* __restrict__ out)
{
    __shared__ float Ah[128*SLD], Al[128*SLD], Bh[128*SLD], Bl[128*SLD];
    const int tid = threadIdx.x;
    const int m0 = blockIdx.y * 128;
    const int d0 = blockIdx.x * 128;
    const int warp = tid >> 5;
    const int wm = (warp & 1) * 64;
    const int wn = (warp >> 1) * 32;

    const int row0 = tid >> 2;
    const int c40  = (tid & 3) * 4;

    const float* ap0 = g_states + (size_t)(m0 + row0)*SDIM + c40;
    const float* ap1 = g_states + (size_t)(m0 + row0 + 64)*SDIM + c40;
    const float* bp0 = Wo + (size_t)(d0 + row0)*SDIM + c40;
    const float* bp1 = Wo + (size_t)(d0 + row0 + 64)*SDIM + c40;

    FragC c[4][2];
#pragma unroll
    for (int i = 0; i < 4; i++)
#pragma unroll
        for (int j = 0; j < 2; j++) wmma::fill_fragment(c[i][j], 0.0f);

    float4 ra0 = *(const float4*)(ap0);
    float4 ra1 = *(const float4*)(ap1);
    float4 rb0 = *(const float4*)(bp0);
    float4 rb1 = *(const float4*)(bp1);

    for (int k0 = 0; k0 < SDIM; k0 += 16) {
        split_store(Ah, Al,  row0     *SLD + c40, ra0);
        split_store(Ah, Al, (row0+64) *SLD + c40, ra1);
        split_store(Bh, Bl,  row0     *SLD + c40, rb0);
        split_store(Bh, Bl, (row0+64) *SLD + c40, rb1);
        __syncthreads();
        int kn = (k0 + 16 < SDIM) ? k0 + 16 : 0;
        ra0 = *(const float4*)(ap0 + kn);
        ra1 = *(const float4*)(ap1 + kn);
        rb0 = *(const float4*)(bp0 + kn);
        rb1 = *(const float4*)(bp1 + kn);
        mma_on_chunk(Ah, Al, Bh, Bl, wm, wn, c);
        __syncthreads();
    }

#pragma unroll
    for (int i = 0; i < 4; i++)
#pragma unroll
        for (int j = 0; j < 2; j++)
            wmma::store_matrix_sync(out + (size_t)(m0 + wm + i*16)*DIM + (d0 + wn + j*16),
                                    c[i][j], DIM, wmma::mem_row_major);
}

// ---------------------------------------------------------------------------
extern "C" void kernel_launch(void* const* d_in, const int* in_sizes, int n_in,
                              void* d_out, int out_size)
{
    const float* x   = (const float*)d_in[0];
    const float* td  = (const float*)d_in[1];
    const float* tf  = (const float*)d_in[2];
    const float* Wk  = (const float*)d_in[3];
    const float* Wv  = (const float*)d_in[4];
    const float* Wo  = (const float*)d_in[5];
    const float* Wsh = (const float*)d_in[6];
    const float* sg  = (const float*)d_in[7];
    const float* lnw = (const float*)d_in[8];
    const float* lnb = (const float*)d_in[9];

    float* out  = (float*)d_out;
    float* last = out + (size_t)MTOT * DIM;

    k_shift_gemm<<<dim3(DIM/128, MTOT/128), 256>>>(x, Wsh);   // n fastest -> A reuse in L2
    k_ln<<<MTOT, 256>>>(x, sg, lnw, lnb);
    k_kv_gemm<<<dim3(1, MTOT/128), 256>>>(Wk, Wv);
    k_wkv<<<(MTOT * SDIM + 255) / 256, 256>>>(tf);
    k_rec_lasts<<<dim3(NCH, BATCH), SDIM>>>(td);
    k_rec_carry<<<BATCH, SDIM>>>(td, last);
    k_rec_scan<<<dim3(NCH, BATCH), SDIM>>>(td);
    k_out_gemm<<<dim3(DIM/128, MTOT/128), 256>>>(Wo, out);
}

// round 4
// speedup vs baseline: 3.9549x; 3.9549x over previous
#include <cuda_runtime.h>
#include <cuda_bf16.h>
#include <math.h>
#include <stdint.h>

#define BATCH  8
#define SEQ    4096
#define DIM    1024
#define SDIM   64
#define SHIFTN 2048
#define MTOT   (BATCH*SEQ)   /* 32768 */
#define CH     512
#define NCH    (SEQ/CH)      /* 8 */

#define TM 128
#define TN 128
#define KC 64                 /* K per chunk (bf16) = 128B rows */
#define TILE_B 16384          /* 128 rows * 128 bytes */
#define STAGE  (4*TILE_B)     /* Ah, Al, Bh, Bl = 64 KB */

// ---------------------------------------------------------------------------
// Device scratch
// ---------------------------------------------------------------------------
__device__ float g_xs[(size_t)MTOT * DIM];
__device__ __align__(16) __nv_bfloat16 g_xh[(size_t)MTOT * DIM];
__device__ __align__(16) __nv_bfloat16 g_xl[(size_t)MTOT * DIM];
__device__ __align__(16) __nv_bfloat16 g_xnh[(size_t)MTOT * DIM];
__device__ __align__(16) __nv_bfloat16 g_xnl[(size_t)MTOT * DIM];
__device__ __align__(16) __nv_bfloat16 g_Wshh[(size_t)DIM * DIM];
__device__ __align__(16) __nv_bfloat16 g_Wshl[(size_t)DIM * DIM];
__device__ __align__(16) __nv_bfloat16 g_Wkvh[128 * DIM];   /* interleaved k/v rows */
__device__ __align__(16) __nv_bfloat16 g_Wkvl[128 * DIM];
__device__ __align__(16) __nv_bfloat16 g_Woh[DIM * SDIM];
__device__ __align__(16) __nv_bfloat16 g_Wol[DIM * SDIM];
__device__ float g_wkv[(size_t)MTOT * SDIM];
__device__ __align__(16) __nv_bfloat16 g_sth[(size_t)MTOT * SDIM];
__device__ __align__(16) __nv_bfloat16 g_stl[(size_t)MTOT * SDIM];
__device__ float g_lasts[BATCH * NCH * SDIM];
__device__ float g_carry[BATCH * NCH * SDIM];

// ---------------------------------------------------------------------------
// PTX helpers (portable: sm_80-level PTX only, no arch-specific features)
// ---------------------------------------------------------------------------
__device__ __forceinline__ uint32_t smem_u32(const void* p) {
    uint32_t a;
    asm("{ .reg .u64 t; cvta.to.shared.u64 t, %1; cvt.u32.u64 %0, t; }"
        : "=r"(a) : "l"(p));
    return a;
}
__device__ __forceinline__ void cp16(uint32_t d, const void* s) {
    asm volatile("cp.async.cg.shared.global [%0], [%1], 16;" :: "r"(d), "l"(s));
}
__device__ __forceinline__ void cp_commit() { asm volatile("cp.async.commit_group;"); }
__device__ __forceinline__ void cp_wait0()  { asm volatile("cp.async.wait_group 0;"); }

__device__ __forceinline__ void ldsm4(uint32_t* r, uint32_t a) {
    asm volatile("ldmatrix.sync.aligned.m8n8.x4.shared.b16 {%0,%1,%2,%3}, [%4];"
                 : "=r"(r[0]), "=r"(r[1]), "=r"(r[2]), "=r"(r[3]) : "r"(a));
}
__device__ __forceinline__ void mma16816(float* c, const uint32_t* a, const uint32_t* b) {
    asm volatile(
        "mma.sync.aligned.m16n8k16.row.col.f32.bf16.bf16.f32 "
        "{%0,%1,%2,%3}, {%4,%5,%6,%7}, {%8,%9}, {%0,%1,%2,%3};"
        : "+f"(c[0]), "+f"(c[1]), "+f"(c[2]), "+f"(c[3])
        : "r"(a[0]), "r"(a[1]), "r"(a[2]), "r"(a[3]), "r"(b[0]), "r"(b[1]));
}

// One 64-wide K chunk: 4 k16 steps, 3-term split, warp tile 64x32 (4m x 4n of 16x8)
__device__ __forceinline__ void mma_stage(uint32_t base, int wm, int wn, int lane,
                                          float C[4][4][4])
{
    const int ra = lane & 15;            // A relative row
    const int ha = lane >> 4;            // A k-half
    const int gq = lane >> 3;
    const int rb = ((gq >> 1) * 8) + (lane & 7);   // B relative n row
    const int hb = gq & 1;               // B k-half
#pragma unroll
    for (int s = 0; s < 4; s++) {
        uint32_t ah[4][4], al[4][4], bh[2][4], bl[2][4];
        const int ca = 2 * s + ha;
        const int cb = 2 * s + hb;
#pragma unroll
        for (int i = 0; i < 4; i++) {
            int r = wm + i * 16 + ra;
            uint32_t ad = base + r * 128 + ((ca ^ (r & 7)) << 4);
            ldsm4(ah[i], ad);
            ldsm4(al[i], ad + TILE_B);
        }
#pragma unroll
        for (int p = 0; p < 2; p++) {
            int n = wn + p * 16 + rb;
            uint32_t bd = base + 2 * TILE_B + n * 128 + ((cb ^ (n & 7)) << 4);
            ldsm4(bh[p], bd);
            ldsm4(bl[p], bd + TILE_B);
        }
#pragma unroll
        for (int i = 0; i < 4; i++)
#pragma unroll
            for (int j = 0; j < 4; j++) {
                const uint32_t* Bh = &bh[j >> 1][(j & 1) * 2];
                const uint32_t* Bl = &bl[j >> 1][(j & 1) * 2];
                mma16816(C[i][j], ah[i], Bh);
                mma16816(C[i][j], ah[i], Bl);
                mma16816(C[i][j], al[i], Bh);
            }
    }
}

// ---------------------------------------------------------------------------
// Prep kernels: fp32 -> bf16 hi/lo
// ---------------------------------------------------------------------------
union U8 { uint4 u; __nv_bfloat16 b[8]; };

__device__ __forceinline__ void split8(const float* f, uint4* dh, uint4* dl) {
    U8 H, L;
#pragma unroll
    for (int j = 0; j < 8; j++) {
        __nv_bfloat16 h = __float2bfloat16(f[j]);
        H.b[j] = h;
        L.b[j] = __float2bfloat16(f[j] - __bfloat162float(h));
    }
    *dh = H.u; *dl = L.u;
}

__global__ void k_prep_x(const float* __restrict__ x) {
    size_t i = ((size_t)blockIdx.x * 256 + threadIdx.x) * 8;
    float f[8];
    *(float4*)(f)     = *(const float4*)(x + i);
    *(float4*)(f + 4) = *(const float4*)(x + i + 4);
    split8(f, (uint4*)(g_xh + i), (uint4*)(g_xl + i));
}
__global__ void k_prep_wsh(const float* __restrict__ w) {
    size_t i = ((size_t)blockIdx.x * 256 + threadIdx.x) * 8;
    float f[8];
    *(float4*)(f)     = *(const float4*)(w + i);
    *(float4*)(f + 4) = *(const float4*)(w + i + 4);
    split8(f, (uint4*)(g_Wshh + i), (uint4*)(g_Wshl + i));
}
__global__ void k_prep_wo(const float* __restrict__ w) {
    size_t i = ((size_t)blockIdx.x * 256 + threadIdx.x) * 8;
    float f[8];
    *(float4*)(f)     = *(const float4*)(w + i);
    *(float4*)(f + 4) = *(const float4*)(w + i + 4);
    split8(f, (uint4*)(g_Woh + i), (uint4*)(g_Wol + i));
}
__global__ void k_prep_wkv(const float* __restrict__ Wk, const float* __restrict__ Wv) {
    size_t i = ((size_t)blockIdx.x * 256 + threadIdx.x) * 8;
    int row = (int)(i >> 10);
    int col = (int)(i & 1023);
    const float* src = ((row & 1) ? Wv : Wk) + (size_t)(row >> 1) * DIM + col;
    float f[8];
    *(float4*)(f)     = *(const float4*)(src);
    *(float4*)(f + 4) = *(const float4*)(src + 4);
    split8(f, (uint4*)(g_Wkvh + i), (uint4*)(g_Wkvl + i));
}

// ---------------------------------------------------------------------------
// GEMM 1: g_xs[m, e] = x_cat[m, :] @ W_shift[e, :]
// ---------------------------------------------------------------------------
__global__ __launch_bounds__(256)
void k_gemm_shift()
{
    extern __shared__ __align__(128) char smc[];
    const uint32_t sbase = smem_u32(smc);
    const int tid = threadIdx.x;
    const int warp = tid >> 5, lane = tid & 31;
    const int wm = (warp & 1) * 64, wn = (warp >> 1) * 32;
    const int m0 = blockIdx.y * TM, e0 = blockIdx.x * TN;

    const int grp = tid & 7;
    const __nv_bfloat16 *pAh[4], *pAl[4], *pBh[4], *pBl[4];
    uint32_t soff[4];
#pragma unroll
    for (int i = 0; i < 4; i++) {
        int r = (tid >> 3) + i * 32;
        int m = m0 + r;
        int b = m >> 12, t = m & 4095;
        int ts = (t + SHIFTN) & 4095;
        size_t ar = ((size_t)((b << 12) + ts)) * DIM + grp * 8;
        pAh[i] = g_xh + ar; pAl[i] = g_xl + ar;
        size_t br = (size_t)(e0 + r) * DIM + grp * 8;
        pBh[i] = g_Wshh + br; pBl[i] = g_Wshl + br;
        soff[i] = r * 128 + ((grp ^ (r & 7)) << 4);
    }

    float C[4][4][4];
#pragma unroll
    for (int i = 0; i < 4; i++)
#pragma unroll
        for (int j = 0; j < 4; j++)
#pragma unroll
            for (int q = 0; q < 4; q++) C[i][j][q] = 0.f;

#pragma unroll
    for (int i = 0; i < 4; i++) {
        uint32_t d = sbase + soff[i];
        cp16(d,              pAh[i]); cp16(d + TILE_B,     pAl[i]);
        cp16(d + 2 * TILE_B, pBh[i]); cp16(d + 3 * TILE_B, pBl[i]);
    }
    cp_commit();

    for (int c = 0; c < 16; c++) {
        int cur = c & 1;
        cp_wait0();
        __syncthreads();
        if (c + 1 < 16) {
            int k0 = (c + 1) * KC;
            uint32_t sb = sbase + ((c + 1) & 1) * STAGE;
#pragma unroll
            for (int i = 0; i < 4; i++) {
                uint32_t d = sb + soff[i];
                cp16(d,              pAh[i] + k0); cp16(d + TILE_B,     pAl[i] + k0);
                cp16(d + 2 * TILE_B, pBh[i] + k0); cp16(d + 3 * TILE_B, pBl[i] + k0);
            }
            cp_commit();
        }
        mma_stage(sbase + cur * STAGE, wm, wn, lane, C);
        __syncthreads();
    }

#pragma unroll
    for (int i = 0; i < 4; i++)
#pragma unroll
        for (int j = 0; j < 4; j++) {
            int r0 = m0 + wm + i * 16 + (lane >> 2);
            int col = e0 + wn + j * 8 + (lane & 3) * 2;
            *(float2*)&g_xs[(size_t)r0 * DIM + col] =
                make_float2(C[i][j][0], C[i][j][1]);
            *(float2*)&g_xs[(size_t)(r0 + 8) * DIM + col] =
                make_float2(C[i][j][2], C[i][j][3]);
        }
}

// ---------------------------------------------------------------------------
// blend + layernorm -> bf16 hi/lo xn
// ---------------------------------------------------------------------------
__inline__ __device__ float warp_sum(float v) {
#pragma unroll
    for (int o = 16; o > 0; o >>= 1) v += __shfl_xor_sync(0xffffffffu, v, o);
    return v;
}

union U4 { uint2 u; __nv_bfloat16 b[4]; };

__global__ __launch_bounds__(256)
void k_ln(const float* __restrict__ x, const float* __restrict__ sg,
          const float* __restrict__ lnw, const float* __restrict__ lnb)
{
    int m = blockIdx.x;
    int tid = threadIdx.x;
    const float4* row = (const float4*)(g_xs + (size_t)m * DIM);
    float4 v  = row[tid];
    float4 xv = ((const float4*)(x + (size_t)m * DIM))[tid];
    float4 gv = ((const float4*)sg)[tid];
    float g0 = 1.f/(1.f+expf(-gv.x)), g1 = 1.f/(1.f+expf(-gv.y));
    float g2 = 1.f/(1.f+expf(-gv.z)), g3 = 1.f/(1.f+expf(-gv.w));
    v.x = v.x*g0 + xv.x*(1.f-g0);
    v.y = v.y*g1 + xv.y*(1.f-g1);
    v.z = v.z*g2 + xv.z*(1.f-g2);
    v.w = v.w*g3 + xv.w*(1.f-g3);

    float s  = v.x + v.y + v.z + v.w;
    float ss = fmaf(v.x, v.x, fmaf(v.y, v.y, fmaf(v.z, v.z, v.w * v.w)));
    s = warp_sum(s); ss = warp_sum(ss);
    __shared__ float sh_s[8], sh_ss[8];
    int wid = tid >> 5, lane = tid & 31;
    if (lane == 0) { sh_s[wid] = s; sh_ss[wid] = ss; }
    __syncthreads();
    if (wid == 0) {
        float a = (lane < 8) ? sh_s[lane] : 0.f;
        float b = (lane < 8) ? sh_ss[lane] : 0.f;
        a = warp_sum(a); b = warp_sum(b);
        if (lane == 0) { sh_s[0] = a; sh_ss[0] = b; }
    }
    __syncthreads();
    float mu  = sh_s[0] * (1.f / DIM);
    float var = sh_ss[0] * (1.f / DIM) - mu * mu;
    float rstd = rsqrtf(var + 1e-5f);
    float4 w4 = ((const float4*)lnw)[tid];
    float4 b4 = ((const float4*)lnb)[tid];
    float f[4];
    f[0] = (v.x - mu) * rstd * w4.x + b4.x;
    f[1] = (v.y - mu) * rstd * w4.y + b4.y;
    f[2] = (v.z - mu) * rstd * w4.z + b4.z;
    f[3] = (v.w - mu) * rstd * w4.w + b4.w;
    U4 H, L;
#pragma unroll
    for (int j = 0; j < 4; j++) {
        __nv_bfloat16 h = __float2bfloat16(f[j]);
        H.b[j] = h;
        L.b[j] = __float2bfloat16(f[j] - __bfloat162float(h));
    }
    size_t off = (size_t)m * DIM + tid * 4;
    *(uint2*)(g_xnh + off) = H.u;
    *(uint2*)(g_xnl + off) = L.u;
}

// ---------------------------------------------------------------------------
// GEMM 2: [k|v] interleaved = xn @ Wkv^T, fused wkv epilogue
// ---------------------------------------------------------------------------
__global__ __launch_bounds__(256)
void k_gemm_kv(const float* __restrict__ time_first)
{
    extern __shared__ __align__(128) char smc[];
    const uint32_t sbase = smem_u32(smc);
    const int tid = threadIdx.x;
    const int warp = tid >> 5, lane = tid & 31;
    const int wm = (warp & 1) * 64, wn = (warp >> 1) * 32;
    const int m0 = blockIdx.y * TM;

    const int grp = tid & 7;
    const __nv_bfloat16 *pAh[4], *pAl[4], *pBh[4], *pBl[4];
    uint32_t soff[4];
#pragma unroll
    for (int i = 0; i < 4; i++) {
        int r = (tid >> 3) + i * 32;
        size_t ar = (size_t)(m0 + r) * DIM + grp * 8;
        pAh[i] = g_xnh + ar; pAl[i] = g_xnl + ar;
        size_t br = (size_t)r * DIM + grp * 8;
        pBh[i] = g_Wkvh + br; pBl[i] = g_Wkvl + br;
        soff[i] = r * 128 + ((grp ^ (r & 7)) << 4);
    }

    float C[4][4][4];
#pragma unroll
    for (int i = 0; i < 4; i++)
#pragma unroll
        for (int j = 0; j < 4; j++)
#pragma unroll
            for (int q = 0; q < 4; q++) C[i][j][q] = 0.f;

#pragma unroll
    for (int i = 0; i < 4; i++) {
        uint32_t d = sbase + soff[i];
        cp16(d,              pAh[i]); cp16(d + TILE_B,     pAl[i]);
        cp16(d + 2 * TILE_B, pBh[i]); cp16(d + 3 * TILE_B, pBl[i]);
    }
    cp_commit();

    for (int c = 0; c < 16; c++) {
        int cur = c & 1;
        cp_wait0();
        __syncthreads();
        if (c + 1 < 16) {
            int k0 = (c + 1) * KC;
            uint32_t sb = sbase + ((c + 1) & 1) * STAGE;
#pragma unroll
            for (int i = 0; i < 4; i++) {
                uint32_t d = sb + soff[i];
                cp16(d,              pAh[i] + k0); cp16(d + TILE_B,     pAl[i] + k0);
                cp16(d + 2 * TILE_B, pBh[i] + k0); cp16(d + 3 * TILE_B, pBl[i] + k0);
            }
            cp_commit();
        }
        mma_stage(sbase + cur * STAGE, wm, wn, lane, C);
        __syncthreads();
    }

    // C cols: even = k_s, odd = v_s (interleaved weights)
#pragma unroll
    for (int i = 0; i < 4; i++)
#pragma unroll
        for (int j = 0; j < 4; j++) {
            int r0 = m0 + wm + i * 16 + (lane >> 2);
            int sidx = (wn >> 1) + j * 4 + (lane & 3);
            float ex = expf(time_first[sidx]);
            float k0v = C[i][j][0], v0v = C[i][j][1];
            float k1v = C[i][j][2], v1v = C[i][j][3];
            float w0 = expf(-ex * (1.f / (1.f + expf(-k0v)))) * v0v;
            float w1 = expf(-ex * (1.f / (1.f + expf(-k1v)))) * v1v;
            g_wkv[(size_t)r0 * SDIM + sidx]       = w0;
            g_wkv[(size_t)(r0 + 8) * SDIM + sidx] = w1;
        }
}

// ---------------------------------------------------------------------------
// Recurrence (chunked scan)
// ---------------------------------------------------------------------------
__global__ void k_rec_lasts(const float* __restrict__ td)
{
    int ch = blockIdx.x, b = blockIdx.y, s = threadIdx.x;
    float w = expf(td[s]);
    const float* wp = g_wkv + ((size_t)(b * SEQ + ch * CH)) * SDIM + s;
    float st = 0.f;
#pragma unroll 8
    for (int t = 0; t < CH; t++) st = fmaf(st, w, wp[(size_t)t * SDIM]);
    g_lasts[(b * NCH + ch) * SDIM + s] = st;
}

__global__ void k_rec_carry(const float* __restrict__ td, float* __restrict__ last_out)
{
    int b = blockIdx.x, s = threadIdx.x;
    float wC = expf((float)CH * td[s]);
    float st = 0.f;
    for (int c = 0; c < NCH; c++) {
        g_carry[(b * NCH + c) * SDIM + s] = st;
        st = st * wC + g_lasts[(b * NCH + c) * SDIM + s];
    }
    last_out[b * SDIM + s] = st;
}

__global__ void k_rec_scan(const float* __restrict__ td)
{
    int ch = blockIdx.x, b = blockIdx.y, s = threadIdx.x;
    float w = expf(td[s]);
    float st = g_carry[(b * NCH + ch) * SDIM + s];
    size_t base = ((size_t)(b * SEQ + ch * CH)) * SDIM + s;
    const float* wp = g_wkv + base;
#pragma unroll 8
    for (int t = 0; t < CH; t++) {
        st = fmaf(st, w, wp[(size_t)t * SDIM]);
        __nv_bfloat16 h = __float2bfloat16(st);
        g_sth[base + (size_t)t * SDIM] = h;
        g_stl[base + (size_t)t * SDIM] = __float2bfloat16(st - __bfloat162float(h));
    }
}

// ---------------------------------------------------------------------------
// GEMM 3: out = states @ Wo^T  (K = 64, single chunk)
// ---------------------------------------------------------------------------
__global__ __launch_bounds__(256)
void k_gemm_out(float* __restrict__ out)
{
    extern __shared__ __align__(128) char smc[];
    const uint32_t sbase = smem_u32(smc);
    const int tid = threadIdx.x;
    const int warp = tid >> 5, lane = tid & 31;
    const int wm = (warp & 1) * 64, wn = (warp >> 1) * 32;
    const int m0 = blockIdx.y * TM, d0 = blockIdx.x * TN;

    const int grp = tid & 7;
#pragma unroll
    for (int i = 0; i < 4; i++) {
        int r = (tid >> 3) + i * 32;
        uint32_t so = r * 128 + ((grp ^ (r & 7)) << 4);
        uint32_t d = sbase + so;
        cp16(d,              g_sth + (size_t)(m0 + r) * SDIM + grp * 8);
        cp16(d + TILE_B,     g_stl + (size_t)(m0 + r) * SDIM + grp * 8);
        cp16(d + 2 * TILE_B, g_Woh + (size_t)(d0 + r) * SDIM + grp * 8);
        cp16(d + 3 * TILE_B, g_Wol + (size_t)(d0 + r) * SDIM + grp * 8);
    }
    cp_commit();

    float C[4][4][4];
#pragma unroll
    for (int i = 0; i < 4; i++)
#pragma unroll
        for (int j = 0; j < 4; j++)
#pragma unroll
            for (int q = 0; q < 4; q++) C[i][j][q] = 0.f;

    cp_wait0();
    __syncthreads();
    mma_stage(sbase, wm, wn, lane, C);

#pragma unroll
    for (int i = 0; i < 4; i++)
#pragma unroll
        for (int j = 0; j < 4; j++) {
            int r0 = m0 + wm + i * 16 + (lane >> 2);
            int col = d0 + wn + j * 8 + (lane & 3) * 2;
            *(float2*)&out[(size_t)r0 * DIM + col] =
                make_float2(C[i][j][0], C[i][j][1]);
            *(float2*)&out[(size_t)(r0 + 8) * DIM + col] =
                make_float2(C[i][j][2], C[i][j][3]);
        }
}

// ---------------------------------------------------------------------------
extern "C" void kernel_launch(void* const* d_in, const int* in_sizes, int n_in,
                              void* d_out, int out_size)
{
    const float* x   = (const float*)d_in[0];
    const float* td  = (const float*)d_in[1];
    const float* tf  = (const float*)d_in[2];
    const float* Wk  = (const float*)d_in[3];
    const float* Wv  = (const float*)d_in[4];
    const float* Wo  = (const float*)d_in[5];
    const float* Wsh = (const float*)d_in[6];
    const float* sg  = (const float*)d_in[7];
    const float* lnw = (const float*)d_in[8];
    const float* lnb = (const float*)d_in[9];

    float* out  = (float*)d_out;
    float* last = out + (size_t)MTOT * DIM;

    const int SMEM2 = 2 * STAGE;   // 128 KB
    const int SMEM1 = STAGE;       // 64 KB
    cudaFuncSetAttribute(k_gemm_shift, cudaFuncAttributeMaxDynamicSharedMemorySize, SMEM2);
    cudaFuncSetAttribute(k_gemm_kv,    cudaFuncAttributeMaxDynamicSharedMemorySize, SMEM2);
    cudaFuncSetAttribute(k_gemm_out,   cudaFuncAttributeMaxDynamicSharedMemorySize, SMEM1);

    k_prep_x  <<<16384, 256>>>(x);
    k_prep_wsh<<<512,   256>>>(Wsh);
    k_prep_wkv<<<64,    256>>>(Wk, Wv);
    k_prep_wo <<<32,    256>>>(Wo);

    k_gemm_shift<<<dim3(DIM / TN, MTOT / TM), 256, SMEM2>>>();
    k_ln<<<MTOT, 256>>>(x, sg, lnw, lnb);
    k_gemm_kv<<<dim3(1, MTOT / TM), 256, SMEM2>>>(tf);

    k_rec_lasts<<<dim3(NCH, BATCH), SDIM>>>(td);
    k_rec_carry<<<BATCH, SDIM>>>(td, last);
    k_rec_scan <<<dim3(NCH, BATCH), SDIM>>>(td);

    k_gemm_out<<<dim3(DIM / TN, MTOT / TM), 256, SMEM1>>>(out);
}

// round 5
// speedup vs baseline: 4.3211x; 1.0926x over previous
#include <cuda_runtime.h>
#include <cuda_bf16.h>
#include <math.h>
#include <stdint.h>

#define BATCH  8
#define SEQ    4096
#define DIM    1024
#define SDIM   64
#define SHIFTN 2048
#define MTOT   (BATCH*SEQ)   /* 32768 */
#define CH     128
#define NCH    (SEQ/CH)      /* 32 */

#define TM 128
#define TN 128
#define KC 64                 /* K per chunk (bf16) = 128B rows */
#define TILE_B 16384          /* 128 rows * 128 bytes */
#define STAGE  (4*TILE_B)     /* Ah, Al, Bh, Bl = 64 KB */
#define NSTAGE 3

// ---------------------------------------------------------------------------
// Device scratch
// ---------------------------------------------------------------------------
__device__ float g_xs[(size_t)MTOT * DIM];
__device__ __align__(16) __nv_bfloat16 g_xh[(size_t)MTOT * DIM];
__device__ __align__(16) __nv_bfloat16 g_xl[(size_t)MTOT * DIM];
__device__ __align__(16) __nv_bfloat16 g_xnh[(size_t)MTOT * DIM];
__device__ __align__(16) __nv_bfloat16 g_xnl[(size_t)MTOT * DIM];
__device__ __align__(16) __nv_bfloat16 g_Wshh[(size_t)DIM * DIM];
__device__ __align__(16) __nv_bfloat16 g_Wshl[(size_t)DIM * DIM];
__device__ __align__(16) __nv_bfloat16 g_Wkvh[128 * DIM];   /* interleaved k/v rows */
__device__ __align__(16) __nv_bfloat16 g_Wkvl[128 * DIM];
__device__ __align__(16) __nv_bfloat16 g_Woh[DIM * SDIM];
__device__ __align__(16) __nv_bfloat16 g_Wol[DIM * SDIM];
__device__ float g_wkv[(size_t)MTOT * SDIM];
__device__ __align__(16) __nv_bfloat16 g_sth[(size_t)MTOT * SDIM];
__device__ __align__(16) __nv_bfloat16 g_stl[(size_t)MTOT * SDIM];
__device__ float g_lasts[BATCH * NCH * SDIM];
__device__ float g_carry[BATCH * NCH * SDIM];

// ---------------------------------------------------------------------------
// PTX helpers (sm_80-level portable PTX only — virtual arch is compute_103)
// ---------------------------------------------------------------------------
__device__ __forceinline__ uint32_t smem_u32(const void* p) {
    uint32_t a;
    asm("{ .reg .u64 t; cvta.to.shared.u64 t, %1; cvt.u32.u64 %0, t; }"
        : "=r"(a) : "l"(p));
    return a;
}
__device__ __forceinline__ void cp16(uint32_t d, const void* s) {
    asm volatile("cp.async.cg.shared.global [%0], [%1], 16;" :: "r"(d), "l"(s));
}
__device__ __forceinline__ void cp_commit() { asm volatile("cp.async.commit_group;"); }
__device__ __forceinline__ void cp_wait0()  { asm volatile("cp.async.wait_group 0;"); }
__device__ __forceinline__ void cp_wait1()  { asm volatile("cp.async.wait_group 1;"); }

__device__ __forceinline__ void ldsm4(uint32_t* r, uint32_t a) {
    asm volatile("ldmatrix.sync.aligned.m8n8.x4.shared.b16 {%0,%1,%2,%3}, [%4];"
                 : "=r"(r[0]), "=r"(r[1]), "=r"(r[2]), "=r"(r[3]) : "r"(a));
}
__device__ __forceinline__ void mma16816(float* c, const uint32_t* a, const uint32_t* b) {
    asm volatile(
        "mma.sync.aligned.m16n8k16.row.col.f32.bf16.bf16.f32 "
        "{%0,%1,%2,%3}, {%4,%5,%6,%7}, {%8,%9}, {%0,%1,%2,%3};"
        : "+f"(c[0]), "+f"(c[1]), "+f"(c[2]), "+f"(c[3])
        : "r"(a[0]), "r"(a[1]), "r"(a[2]), "r"(a[3]), "r"(b[0]), "r"(b[1]));
}

// One 64-wide K chunk: 4 k16 steps, 3-term split, warp tile 64x32 (4m x 4n of 16x8)
__device__ __forceinline__ void mma_stage(uint32_t base, int wm, int wn, int lane,
                                          float C[4][4][4])
{
    const int ra = lane & 15;
    const int ha = lane >> 4;
    const int gq = lane >> 3;
    const int rb = ((gq >> 1) * 8) + (lane & 7);
    const int hb = gq & 1;
#pragma unroll
    for (int s = 0; s < 4; s++) {
        uint32_t ah[4][4], al[4][4], bh[2][4], bl[2][4];
        const int ca = 2 * s + ha;
        const int cb = 2 * s + hb;
#pragma unroll
        for (int i = 0; i < 4; i++) {
            int r = wm + i * 16 + ra;
            uint32_t ad = base + r * 128 + ((ca ^ (r & 7)) << 4);
            ldsm4(ah[i], ad);
            ldsm4(al[i], ad + TILE_B);
        }
#pragma unroll
        for (int p = 0; p < 2; p++) {
            int n = wn + p * 16 + rb;
            uint32_t bd = base + 2 * TILE_B + n * 128 + ((cb ^ (n & 7)) << 4);
            ldsm4(bh[p], bd);
            ldsm4(bl[p], bd + TILE_B);
        }
#pragma unroll
        for (int i = 0; i < 4; i++)
#pragma unroll
            for (int j = 0; j < 4; j++) {
                const uint32_t* Bh = &bh[j >> 1][(j & 1) * 2];
                const uint32_t* Bl = &bl[j >> 1][(j & 1) * 2];
                mma16816(C[i][j], ah[i], Bh);
                mma16816(C[i][j], ah[i], Bl);
                mma16816(C[i][j], al[i], Bh);
            }
    }
}

// ---------------------------------------------------------------------------
// Prep kernels: fp32 -> bf16 hi/lo
// ---------------------------------------------------------------------------
union U8 { uint4 u; __nv_bfloat16 b[8]; };

__device__ __forceinline__ void split8(const float* f, uint4* dh, uint4* dl) {
    U8 H, L;
#pragma unroll
    for (int j = 0; j < 8; j++) {
        __nv_bfloat16 h = __float2bfloat16(f[j]);
        H.b[j] = h;
        L.b[j] = __float2bfloat16(f[j] - __bfloat162float(h));
    }
    *dh = H.u; *dl = L.u;
}

__global__ void k_prep_x(const float* __restrict__ x) {
    size_t i = ((size_t)blockIdx.x * 256 + threadIdx.x) * 8;
    float f[8];
    *(float4*)(f)     = *(const float4*)(x + i);
    *(float4*)(f + 4) = *(const float4*)(x + i + 4);
    split8(f, (uint4*)(g_xh + i), (uint4*)(g_xl + i));
}
__global__ void k_prep_wsh(const float* __restrict__ w) {
    size_t i = ((size_t)blockIdx.x * 256 + threadIdx.x) * 8;
    float f[8];
    *(float4*)(f)     = *(const float4*)(w + i);
    *(float4*)(f + 4) = *(const float4*)(w + i + 4);
    split8(f, (uint4*)(g_Wshh + i), (uint4*)(g_Wshl + i));
}
__global__ void k_prep_wo(const float* __restrict__ w) {
    size_t i = ((size_t)blockIdx.x * 256 + threadIdx.x) * 8;
    float f[8];
    *(float4*)(f)     = *(const float4*)(w + i);
    *(float4*)(f + 4) = *(const float4*)(w + i + 4);
    split8(f, (uint4*)(g_Woh + i), (uint4*)(g_Wol + i));
}
__global__ void k_prep_wkv(const float* __restrict__ Wk, const float* __restrict__ Wv) {
    size_t i = ((size_t)blockIdx.x * 256 + threadIdx.x) * 8;
    int row = (int)(i >> 10);
    int col = (int)(i & 1023);
    const float* src = ((row & 1) ? Wv : Wk) + (size_t)(row >> 1) * DIM + col;
    float f[8];
    *(float4*)(f)     = *(const float4*)(src);
    *(float4*)(f + 4) = *(const float4*)(src + 4);
    split8(f, (uint4*)(g_Wkvh + i), (uint4*)(g_Wkvl + i));
}

// ---------------------------------------------------------------------------
// GEMM 1: g_xs[m, e] = x_cat[m, :] @ W_shift[e, :]   (3-stage pipeline)
// ---------------------------------------------------------------------------
__global__ __launch_bounds__(256)
void k_gemm_shift()
{
    extern __shared__ __align__(128) char smc[];
    const uint32_t sbase = smem_u32(smc);
    const int tid = threadIdx.x;
    const int warp = tid >> 5, lane = tid & 31;
    const int wm = (warp & 1) * 64, wn = (warp >> 1) * 32;
    const int m0 = blockIdx.y * TM, e0 = blockIdx.x * TN;

    const int grp = tid & 7;
    const __nv_bfloat16 *pAh[4], *pAl[4], *pBh[4], *pBl[4];
    uint32_t soff[4];
#pragma unroll
    for (int i = 0; i < 4; i++) {
        int r = (tid >> 3) + i * 32;
        int m = m0 + r;
        int b = m >> 12, t = m & 4095;
        int ts = (t + SHIFTN) & 4095;
        size_t ar = ((size_t)((b << 12) + ts)) * DIM + grp * 8;
        pAh[i] = g_xh + ar; pAl[i] = g_xl + ar;
        size_t br = (size_t)(e0 + r) * DIM + grp * 8;
        pBh[i] = g_Wshh + br; pBl[i] = g_Wshl + br;
        soff[i] = r * 128 + ((grp ^ (r & 7)) << 4);
    }

    float C[4][4][4];
#pragma unroll
    for (int i = 0; i < 4; i++)
#pragma unroll
        for (int j = 0; j < 4; j++)
#pragma unroll
            for (int q = 0; q < 4; q++) C[i][j][q] = 0.f;

    // prologue: stages 0 and 1
#pragma unroll
    for (int pc = 0; pc < 2; pc++) {
        uint32_t sb = sbase + pc * STAGE;
        int k0 = pc * KC;
#pragma unroll
        for (int i = 0; i < 4; i++) {
            uint32_t d = sb + soff[i];
            cp16(d,              pAh[i] + k0); cp16(d + TILE_B,     pAl[i] + k0);
            cp16(d + 2 * TILE_B, pBh[i] + k0); cp16(d + 3 * TILE_B, pBl[i] + k0);
        }
        cp_commit();
    }

    const int NC = 16;
    int buf = 0;
    for (int c = 0; c < NC; c++) {
        if (c == NC - 1) cp_wait0(); else cp_wait1();
        __syncthreads();
        if (c + 2 < NC) {
            int k0 = (c + 2) * KC;
            int nb = buf + 2; if (nb >= NSTAGE) nb -= NSTAGE;
            uint32_t sb = sbase + nb * STAGE;
#pragma unroll
            for (int i = 0; i < 4; i++) {
                uint32_t d = sb + soff[i];
                cp16(d,              pAh[i] + k0); cp16(d + TILE_B,     pAl[i] + k0);
                cp16(d + 2 * TILE_B, pBh[i] + k0); cp16(d + 3 * TILE_B, pBl[i] + k0);
            }
            cp_commit();
        }
        mma_stage(sbase + buf * STAGE, wm, wn, lane, C);
        __syncthreads();
        if (++buf == NSTAGE) buf = 0;
    }

#pragma unroll
    for (int i = 0; i < 4; i++)
#pragma unroll
        for (int j = 0; j < 4; j++) {
            int r0 = m0 + wm + i * 16 + (lane >> 2);
            int col = e0 + wn + j * 8 + (lane & 3) * 2;
            *(float2*)&g_xs[(size_t)r0 * DIM + col] =
                make_float2(C[i][j][0], C[i][j][1]);
            *(float2*)&g_xs[(size_t)(r0 + 8) * DIM + col] =
                make_float2(C[i][j][2], C[i][j][3]);
        }
}

// ---------------------------------------------------------------------------
// blend + layernorm -> bf16 hi/lo xn
// ---------------------------------------------------------------------------
__inline__ __device__ float warp_sum(float v) {
#pragma unroll
    for (int o = 16; o > 0; o >>= 1) v += __shfl_xor_sync(0xffffffffu, v, o);
    return v;
}

union U4 { uint2 u; __nv_bfloat16 b[4]; };

__global__ __launch_bounds__(256)
void k_ln(const float* __restrict__ x, const float* __restrict__ sg,
          const float* __restrict__ lnw, const float* __restrict__ lnb)
{
    int m = blockIdx.x;
    int tid = threadIdx.x;
    const float4* row = (const float4*)(g_xs + (size_t)m * DIM);
    float4 v  = row[tid];
    float4 xv = ((const float4*)(x + (size_t)m * DIM))[tid];
    float4 gv = ((const float4*)sg)[tid];
    float g0 = 1.f/(1.f+expf(-gv.x)), g1 = 1.f/(1.f+expf(-gv.y));
    float g2 = 1.f/(1.f+expf(-gv.z)), g3 = 1.f/(1.f+expf(-gv.w));
    v.x = v.x*g0 + xv.x*(1.f-g0);
    v.y = v.y*g1 + xv.y*(1.f-g1);
    v.z = v.z*g2 + xv.z*(1.f-g2);
    v.w = v.w*g3 + xv.w*(1.f-g3);

    float s  = v.x + v.y + v.z + v.w;
    float ss = fmaf(v.x, v.x, fmaf(v.y, v.y, fmaf(v.z, v.z, v.w * v.w)));
    s = warp_sum(s); ss = warp_sum(ss);
    __shared__ float sh_s[8], sh_ss[8];
    int wid = tid >> 5, lane = tid & 31;
    if (lane == 0) { sh_s[wid] = s; sh_ss[wid] = ss; }
    __syncthreads();
    if (wid == 0) {
        float a = (lane < 8) ? sh_s[lane] : 0.f;
        float b = (lane < 8) ? sh_ss[lane] : 0.f;
        a = warp_sum(a); b = warp_sum(b);
        if (lane == 0) { sh_s[0] = a; sh_ss[0] = b; }
    }
    __syncthreads();
    float mu  = sh_s[0] * (1.f / DIM);
    float var = sh_ss[0] * (1.f / DIM) - mu * mu;
    float rstd = rsqrtf(var + 1e-5f);
    float4 w4 = ((const float4*)lnw)[tid];
    float4 b4 = ((const float4*)lnb)[tid];
    float f[4];
    f[0] = (v.x - mu) * rstd * w4.x + b4.x;
    f[1] = (v.y - mu) * rstd * w4.y + b4.y;
    f[2] = (v.z - mu) * rstd * w4.z + b4.z;
    f[3] = (v.w - mu) * rstd * w4.w + b4.w;
    U4 H, L;
#pragma unroll
    for (int j = 0; j < 4; j++) {
        __nv_bfloat16 h = __float2bfloat16(f[j]);
        H.b[j] = h;
        L.b[j] = __float2bfloat16(f[j] - __bfloat162float(h));
    }
    size_t off = (size_t)m * DIM + tid * 4;
    *(uint2*)(g_xnh + off) = H.u;
    *(uint2*)(g_xnl + off) = L.u;
}

// ---------------------------------------------------------------------------
// GEMM 2: [k|v] interleaved = xn @ Wkv^T, fused wkv epilogue (3-stage)
// ---------------------------------------------------------------------------
__global__ __launch_bounds__(256)
void k_gemm_kv(const float* __restrict__ time_first)
{
    extern __shared__ __align__(128) char smc[];
    const uint32_t sbase = smem_u32(smc);
    const int tid = threadIdx.x;
    const int warp = tid >> 5, lane = tid & 31;
    const int wm = (warp & 1) * 64, wn = (warp >> 1) * 32;
    const int m0 = blockIdx.y * TM;

    const int grp = tid & 7;
    const __nv_bfloat16 *pAh[4], *pAl[4], *pBh[4], *pBl[4];
    uint32_t soff[4];
#pragma unroll
    for (int i = 0; i < 4; i++) {
        int r = (tid >> 3) + i * 32;
        size_t ar = (size_t)(m0 + r) * DIM + grp * 8;
        pAh[i] = g_xnh + ar; pAl[i] = g_xnl + ar;
        size_t br = (size_t)r * DIM + grp * 8;
        pBh[i] = g_Wkvh + br; pBl[i] = g_Wkvl + br;
        soff[i] = r * 128 + ((grp ^ (r & 7)) << 4);
    }

    float C[4][4][4];
#pragma unroll
    for (int i = 0; i < 4; i++)
#pragma unroll
        for (int j = 0; j < 4; j++)
#pragma unroll
            for (int q = 0; q < 4; q++) C[i][j][q] = 0.f;

#pragma unroll
    for (int pc = 0; pc < 2; pc++) {
        uint32_t sb = sbase + pc * STAGE;
        int k0 = pc * KC;
#pragma unroll
        for (int i = 0; i < 4; i++) {
            uint32_t d = sb + soff[i];
            cp16(d,              pAh[i] + k0); cp16(d + TILE_B,     pAl[i] + k0);
            cp16(d + 2 * TILE_B, pBh[i] + k0); cp16(d + 3 * TILE_B, pBl[i] + k0);
        }
        cp_commit();
    }

    const int NC = 16;
    int buf = 0;
    for (int c = 0; c < NC; c++) {
        if (c == NC - 1) cp_wait0(); else cp_wait1();
        __syncthreads();
        if (c + 2 < NC) {
            int k0 = (c + 2) * KC;
            int nb = buf + 2; if (nb >= NSTAGE) nb -= NSTAGE;
            uint32_t sb = sbase + nb * STAGE;
#pragma unroll
            for (int i = 0; i < 4; i++) {
                uint32_t d = sb + soff[i];
                cp16(d,              pAh[i] + k0); cp16(d + TILE_B,     pAl[i] + k0);
                cp16(d + 2 * TILE_B, pBh[i] + k0); cp16(d + 3 * TILE_B, pBl[i] + k0);
            }
            cp_commit();
        }
        mma_stage(sbase + buf * STAGE, wm, wn, lane, C);
        __syncthreads();
        if (++buf == NSTAGE) buf = 0;
    }

    // C cols: even = k_s, odd = v_s (interleaved weights)
#pragma unroll
    for (int i = 0; i < 4; i++)
#pragma unroll
        for (int j = 0; j < 4; j++) {
            int r0 = m0 + wm + i * 16 + (lane >> 2);
            int sidx = (wn >> 1) + j * 4 + (lane & 3);
            float ex = expf(time_first[sidx]);
            float k0v = C[i][j][0], v0v = C[i][j][1];
            float k1v = C[i][j][2], v1v = C[i][j][3];
            float w0 = expf(-ex * (1.f / (1.f + expf(-k0v)))) * v0v;
            float w1 = expf(-ex * (1.f / (1.f + expf(-k1v)))) * v1v;
            g_wkv[(size_t)r0 * SDIM + sidx]       = w0;
            g_wkv[(size_t)(r0 + 8) * SDIM + sidx] = w1;
        }
}

// ---------------------------------------------------------------------------
// Recurrence (chunked scan, CH=128)
// ---------------------------------------------------------------------------
__global__ void k_rec_lasts(const float* __restrict__ td)
{
    int ch = blockIdx.x, b = blockIdx.y, s = threadIdx.x;
    float w = expf(td[s]);
    const float* wp = g_wkv + ((size_t)(b * SEQ + ch * CH)) * SDIM + s;
    float st = 0.f;
#pragma unroll 8
    for (int t = 0; t < CH; t++) st = fmaf(st, w, wp[(size_t)t * SDIM]);
    g_lasts[(b * NCH + ch) * SDIM + s] = st;
}

__global__ void k_rec_carry(const float* __restrict__ td, float* __restrict__ last_out)
{
    int b = blockIdx.x, s = threadIdx.x;
    float wC = expf((float)CH * td[s]);
    float st = 0.f;
    for (int c = 0; c < NCH; c++) {
        g_carry[(b * NCH + c) * SDIM + s] = st;
        st = st * wC + g_lasts[(b * NCH + c) * SDIM + s];
    }
    last_out[b * SDIM + s] = st;
}

__global__ void k_rec_scan(const float* __restrict__ td)
{
    int ch = blockIdx.x, b = blockIdx.y, s = threadIdx.x;
    float w = expf(td[s]);
    float st = g_carry[(b * NCH + ch) * SDIM + s];
    size_t base = ((size_t)(b * SEQ + ch * CH)) * SDIM + s;
    const float* wp = g_wkv + base;
#pragma unroll 8
    for (int t = 0; t < CH; t++) {
        st = fmaf(st, w, wp[(size_t)t * SDIM]);
        __nv_bfloat16 h = __float2bfloat16(st);
        g_sth[base + (size_t)t * SDIM] = h;
        g_stl[base + (size_t)t * SDIM] = __float2bfloat16(st - __bfloat162float(h));
    }
}

// ---------------------------------------------------------------------------
// GEMM 3: out = states @ Wo^T  (K = 64, single chunk)
// ---------------------------------------------------------------------------
__global__ __launch_bounds__(256)
void k_gemm_out(float* __restrict__ out)
{
    extern __shared__ __align__(128) char smc[];
    const uint32_t sbase = smem_u32(smc);
    const int tid = threadIdx.x;
    const int warp = tid >> 5, lane = tid & 31;
    const int wm = (warp & 1) * 64, wn = (warp >> 1) * 32;
    const int m0 = blockIdx.y * TM, d0 = blockIdx.x * TN;

    const int grp = tid & 7;
#pragma unroll
    for (int i = 0; i < 4; i++) {
        int r = (tid >> 3) + i * 32;
        uint32_t so = r * 128 + ((grp ^ (r & 7)) << 4);
        uint32_t d = sbase + so;
        cp16(d,              g_sth + (size_t)(m0 + r) * SDIM + grp * 8);
        cp16(d + TILE_B,     g_stl + (size_t)(m0 + r) * SDIM + grp * 8);
        cp16(d + 2 * TILE_B, g_Woh + (size_t)(d0 + r) * SDIM + grp * 8);
        cp16(d + 3 * TILE_B, g_Wol + (size_t)(d0 + r) * SDIM + grp * 8);
    }
    cp_commit();

    float C[4][4][4];
#pragma unroll
    for (int i = 0; i < 4; i++)
#pragma unroll
        for (int j = 0; j < 4; j++)
#pragma unroll
            for (int q = 0; q < 4; q++) C[i][j][q] = 0.f;

    cp_wait0();
    __syncthreads();
    mma_stage(sbase, wm, wn, lane, C);

#pragma unroll
    for (int i = 0; i < 4; i++)
#pragma unroll
        for (int j = 0; j < 4; j++) {
            int r0 = m0 + wm + i * 16 + (lane >> 2);
            int col = d0 + wn + j * 8 + (lane & 3) * 2;
            *(float2*)&out[(size_t)r0 * DIM + col] =
                make_float2(C[i][j][0], C[i][j][1]);
            *(float2*)&out[(size_t)(r0 + 8) * DIM + col] =
                make_float2(C[i][j][2], C[i][j][3]);
        }
}

// ---------------------------------------------------------------------------
extern "C" void kernel_launch(void* const* d_in, const int* in_sizes, int n_in,
                              void* d_out, int out_size)
{
    const float* x   = (const float*)d_in[0];
    const float* td  = (const float*)d_in[1];
    const float* tf  = (const float*)d_in[2];
    const float* Wk  = (const float*)d_in[3];
    const float* Wv  = (const float*)d_in[4];
    const float* Wo  = (const float*)d_in[5];
    const float* Wsh = (const float*)d_in[6];
    const float* sg  = (const float*)d_in[7];
    const float* lnw = (const float*)d_in[8];
    const float* lnb = (const float*)d_in[9];

    float* out  = (float*)d_out;
    float* last = out + (size_t)MTOT * DIM;

    const int SMEM3 = NSTAGE * STAGE;   // 192 KB
    const int SMEM1 = STAGE;            // 64 KB
    cudaFuncSetAttribute(k_gemm_shift, cudaFuncAttributeMaxDynamicSharedMemorySize, SMEM3);
    cudaFuncSetAttribute(k_gemm_kv,    cudaFuncAttributeMaxDynamicSharedMemorySize, SMEM3);
    cudaFuncSetAttribute(k_gemm_out,   cudaFuncAttributeMaxDynamicSharedMemorySize, SMEM1);

    // launch index 3 = k_gemm_shift -> gets profiled by ncu (-s/-c window)
    k_prep_x  <<<16384, 256>>>(x);
    k_prep_wsh<<<512,   256>>>(Wsh);
    k_prep_wkv<<<64,    256>>>(Wk, Wv);
    k_gemm_shift<<<dim3(DIM / TN, MTOT / TM), 256, SMEM3>>>();

    k_prep_wo <<<32,    256>>>(Wo);
    k_ln<<<MTOT, 256>>>(x, sg, lnw, lnb);
    k_gemm_kv<<<dim3(1, MTOT / TM), 256, SMEM3>>>(tf);

    k_rec_lasts<<<dim3(NCH, BATCH), SDIM>>>(td);
    k_rec_carry<<<BATCH, SDIM>>>(td, last);
    k_rec_scan <<<dim3(NCH, BATCH), SDIM>>>(td);

    k_gemm_out<<<dim3(DIM / TN, MTOT / TM), 256, SMEM1>>>(out);
}

// round 6
// speedup vs baseline: 4.5314x; 1.0487x over previous
#include <cuda_runtime.h>
#include <cuda_bf16.h>
#include <math.h>
#include <stdint.h>

#define BATCH  8
#define SEQ    4096
#define DIM    1024
#define SDIM   64
#define SHIFTN 2048
#define MTOT   (BATCH*SEQ)   /* 32768 */
#define CH     128
#define NCH    (SEQ/CH)      /* 32 */

#define KC 64                 /* K per chunk (bf16) = 128B hi + 128B lo rows */

/* shift GEMM (512 threads): CTA 128x256 */
#define S_TM 128
#define S_TN 256
#define S_AB 16384            /* A subtile bytes (hi) */
#define S_BB 32768            /* B subtile bytes (hi) */
#define S_STAGE (2*S_AB + 2*S_BB)   /* 98304 */

/* kv / out GEMM (256 threads): CTA 128x128 */
#define TILE_B 16384
#define STAGE  (4*TILE_B)     /* 65536 */
#define NSTAGE 3

// ---------------------------------------------------------------------------
// Device scratch — paired hi/lo chunk layout:
// row stride 2*ncols bf16; chunk c: hi at c*128 + w, lo at c*128 + 64 + w
// ---------------------------------------------------------------------------
__device__ float g_xs[(size_t)MTOT * DIM];
__device__ __align__(16) __nv_bfloat16 g_x2[(size_t)MTOT * 2 * DIM];
__device__ __align__(16) __nv_bfloat16 g_xn2[(size_t)MTOT * 2 * DIM];
__device__ __align__(16) __nv_bfloat16 g_Wsh2[(size_t)DIM * 2 * DIM];
__device__ __align__(16) __nv_bfloat16 g_Wkv2[128 * 2 * DIM];   /* interleaved k/v */
__device__ __align__(16) __nv_bfloat16 g_Wo2[DIM * 2 * SDIM];
__device__ __align__(16) __nv_bfloat16 g_st2[(size_t)MTOT * 2 * SDIM];
__device__ float g_wkv[(size_t)MTOT * SDIM];
__device__ float g_lasts[BATCH * NCH * SDIM];
__device__ float g_carry[BATCH * NCH * SDIM];

// ---------------------------------------------------------------------------
// PTX helpers (sm_80-level portable PTX only)
// ---------------------------------------------------------------------------
__device__ __forceinline__ uint32_t smem_u32(const void* p) {
    uint32_t a;
    asm("{ .reg .u64 t; cvta.to.shared.u64 t, %1; cvt.u32.u64 %0, t; }"
        : "=r"(a) : "l"(p));
    return a;
}
__device__ __forceinline__ void cp16(uint32_t d, const void* s) {
    asm volatile("cp.async.cg.shared.global [%0], [%1], 16;" :: "r"(d), "l"(s));
}
__device__ __forceinline__ void cp_commit() { asm volatile("cp.async.commit_group;"); }
__device__ __forceinline__ void cp_wait0()  { asm volatile("cp.async.wait_group 0;"); }
__device__ __forceinline__ void cp_wait1()  { asm volatile("cp.async.wait_group 1;"); }

__device__ __forceinline__ void ldsm4(uint32_t* r, uint32_t a) {
    asm volatile("ldmatrix.sync.aligned.m8n8.x4.shared.b16 {%0,%1,%2,%3}, [%4];"
                 : "=r"(r[0]), "=r"(r[1]), "=r"(r[2]), "=r"(r[3]) : "r"(a));
}
__device__ __forceinline__ void mma16816(float* c, const uint32_t* a, const uint32_t* b) {
    asm volatile(
        "mma.sync.aligned.m16n8k16.row.col.f32.bf16.bf16.f32 "
        "{%0,%1,%2,%3}, {%4,%5,%6,%7}, {%8,%9}, {%0,%1,%2,%3};"
        : "+f"(c[0]), "+f"(c[1]), "+f"(c[2]), "+f"(c[3])
        : "r"(a[0]), "r"(a[1]), "r"(a[2]), "r"(a[3]), "r"(b[0]), "r"(b[1]));
}

// 256-thread variant: warp tile 64x32 (4m x 4n)
__device__ __forceinline__ void mma_stage(uint32_t base, int wm, int wn, int lane,
                                          float C[4][4][4])
{
    const int ra = lane & 15;
    const int ha = lane >> 4;
    const int gq = lane >> 3;
    const int rb = ((gq >> 1) * 8) + (lane & 7);
    const int hb = gq & 1;
#pragma unroll
    for (int s = 0; s < 4; s++) {
        uint32_t ah[4][4], al[4][4], bh[2][4], bl[2][4];
        const int ca = 2 * s + ha;
        const int cb = 2 * s + hb;
#pragma unroll
        for (int i = 0; i < 4; i++) {
            int r = wm + i * 16 + ra;
            uint32_t ad = base + r * 128 + ((ca ^ (r & 7)) << 4);
            ldsm4(ah[i], ad);
            ldsm4(al[i], ad + TILE_B);
        }
#pragma unroll
        for (int p = 0; p < 2; p++) {
            int n = wn + p * 16 + rb;
            uint32_t bd = base + 2 * TILE_B + n * 128 + ((cb ^ (n & 7)) << 4);
            ldsm4(bh[p], bd);
            ldsm4(bl[p], bd + TILE_B);
        }
#pragma unroll
        for (int i = 0; i < 4; i++)
#pragma unroll
            for (int j = 0; j < 4; j++) {
                const uint32_t* Bh = &bh[j >> 1][(j & 1) * 2];
                const uint32_t* Bl = &bl[j >> 1][(j & 1) * 2];
                mma16816(C[i][j], ah[i], Bh);
                mma16816(C[i][j], ah[i], Bl);
                mma16816(C[i][j], al[i], Bh);
            }
    }
}

// 512-thread variant: warp tile 32x64 (2m x 8n); A at base, B at base+2*S_AB
__device__ __forceinline__ void mma_stage_b(uint32_t base, int wm, int wn, int lane,
                                            float C[2][8][4])
{
    const int ra = lane & 15;
    const int ha = lane >> 4;
    const int gq = lane >> 3;
    const int rb = ((gq >> 1) * 8) + (lane & 7);
    const int hb = gq & 1;
#pragma unroll
    for (int s = 0; s < 4; s++) {
        uint32_t ah[2][4], al[2][4], bh[4][4], bl[4][4];
        const int ca = 2 * s + ha;
        const int cb = 2 * s + hb;
#pragma unroll
        for (int i = 0; i < 2; i++) {
            int r = wm + i * 16 + ra;
            uint32_t ad = base + r * 128 + ((ca ^ (r & 7)) << 4);
            ldsm4(ah[i], ad);
            ldsm4(al[i], ad + S_AB);
        }
#pragma unroll
        for (int p = 0; p < 4; p++) {
            int n = wn + p * 16 + rb;
            uint32_t bd = base + 2 * S_AB + n * 128 + ((cb ^ (n & 7)) << 4);
            ldsm4(bh[p], bd);
            ldsm4(bl[p], bd + S_BB);
        }
#pragma unroll
        for (int i = 0; i < 2; i++)
#pragma unroll
            for (int j = 0; j < 8; j++) {
                const uint32_t* Bh = &bh[j >> 1][(j & 1) * 2];
                const uint32_t* Bl = &bl[j >> 1][(j & 1) * 2];
                mma16816(C[i][j], ah[i], Bh);
                mma16816(C[i][j], ah[i], Bl);
                mma16816(C[i][j], al[i], Bh);
            }
    }
}

// ---------------------------------------------------------------------------
// Prep kernels: fp32 -> paired hi/lo bf16 chunk layout
// ---------------------------------------------------------------------------
union U8 { uint4 u; __nv_bfloat16 b[8]; };

__device__ __forceinline__ void split8(const float* f, U8* H, U8* L) {
#pragma unroll
    for (int j = 0; j < 8; j++) {
        __nv_bfloat16 h = __float2bfloat16(f[j]);
        H->b[j] = h;
        L->b[j] = __float2bfloat16(f[j] - __bfloat162float(h));
    }
}

__global__ void k_prep_x(const float* __restrict__ x) {
    size_t i = ((size_t)blockIdx.x * 256 + threadIdx.x) * 8;
    int r = (int)(i >> 10), col = (int)(i & 1023);
    float f[8];
    *(float4*)(f)     = *(const float4*)(x + i);
    *(float4*)(f + 4) = *(const float4*)(x + i + 4);
    U8 H, L; split8(f, &H, &L);
    size_t dst = (size_t)r * 2048 + (col >> 6) * 128 + (col & 63);
    *(uint4*)(g_x2 + dst)      = H.u;
    *(uint4*)(g_x2 + dst + 64) = L.u;
}
__global__ void k_prep_wsh(const float* __restrict__ w) {
    size_t i = ((size_t)blockIdx.x * 256 + threadIdx.x) * 8;
    int r = (int)(i >> 10), col = (int)(i & 1023);
    float f[8];
    *(float4*)(f)     = *(const float4*)(w + i);
    *(float4*)(f + 4) = *(const float4*)(w + i + 4);
    U8 H, L; split8(f, &H, &L);
    size_t dst = (size_t)r * 2048 + (col >> 6) * 128 + (col & 63);
    *(uint4*)(g_Wsh2 + dst)      = H.u;
    *(uint4*)(g_Wsh2 + dst + 64) = L.u;
}
__global__ void k_prep_wo(const float* __restrict__ w) {
    size_t i = ((size_t)blockIdx.x * 256 + threadIdx.x) * 8;
    int r = (int)(i >> 6), s = (int)(i & 63);
    float f[8];
    *(float4*)(f)     = *(const float4*)(w + i);
    *(float4*)(f + 4) = *(const float4*)(w + i + 4);
    U8 H, L; split8(f, &H, &L);
    size_t dst = (size_t)r * 128 + s;
    *(uint4*)(g_Wo2 + dst)      = H.u;
    *(uint4*)(g_Wo2 + dst + 64) = L.u;
}
__global__ void k_prep_wkv(const float* __restrict__ Wk, const float* __restrict__ Wv) {
    size_t i = ((size_t)blockIdx.x * 256 + threadIdx.x) * 8;   /* over 128*1024 */
    int row = (int)(i >> 10), col = (int)(i & 1023);
    const float* src = ((row & 1) ? Wv : Wk) + (size_t)(row >> 1) * DIM + col;
    float f[8];
    *(float4*)(f)     = *(const float4*)(src);
    *(float4*)(f + 4) = *(const float4*)(src + 4);
    U8 H, L; split8(f, &H, &L);
    size_t dst = (size_t)row * 2048 + (col >> 6) * 128 + (col & 63);
    *(uint4*)(g_Wkv2 + dst)      = H.u;
    *(uint4*)(g_Wkv2 + dst + 64) = L.u;
}

// ---------------------------------------------------------------------------
// GEMM 1: g_xs[m, e] = x_cat[m, :] @ W_shift[e, :]
// 512 threads, CTA 128x256, 2-stage pipeline
// ---------------------------------------------------------------------------
__global__ __launch_bounds__(512)
void k_gemm_shift()
{
    extern __shared__ __align__(128) char smc[];
    const uint32_t sbase = smem_u32(smc);
    const int tid = threadIdx.x;
    const int warp = tid >> 5, lane = tid & 31;
    const int wm = (warp & 3) * 32, wn = (warp >> 2) * 64;
    const int m0 = blockIdx.y * S_TM, e0 = blockIdx.x * S_TN;

    const int grp = tid & 7;
    const __nv_bfloat16 *pA[2], *pB[4];
    uint32_t soA[2], soB[4];
#pragma unroll
    for (int i = 0; i < 2; i++) {
        int u = tid + 512 * i;
        int r = u >> 3;
        int m = m0 + r;
        int b = m >> 12, t = m & 4095;
        int ts = (t + SHIFTN) & 4095;
        pA[i] = g_x2 + ((size_t)((b << 12) + ts)) * 2048 + grp * 8;
        soA[i] = r * 128 + ((grp ^ (r & 7)) << 4);
    }
#pragma unroll
    for (int i = 0; i < 4; i++) {
        int u = tid + 512 * i;
        int r = u >> 3;       /* 0..255 */
        pB[i] = g_Wsh2 + (size_t)(e0 + r) * 2048 + grp * 8;
        soB[i] = r * 128 + ((grp ^ (r & 7)) << 4);
    }

    float C[2][8][4];
#pragma unroll
    for (int i = 0; i < 2; i++)
#pragma unroll
        for (int j = 0; j < 8; j++)
#pragma unroll
            for (int q = 0; q < 4; q++) C[i][j][q] = 0.f;

    // prologue: chunk 0 into stage 0
#pragma unroll
    for (int i = 0; i < 2; i++) {
        uint32_t d = sbase + soA[i];
        cp16(d, pA[i]); cp16(d + S_AB, pA[i] + 64);
    }
#pragma unroll
    for (int i = 0; i < 4; i++) {
        uint32_t d = sbase + 2 * S_AB + soB[i];
        cp16(d, pB[i]); cp16(d + S_BB, pB[i] + 64);
    }
    cp_commit();

    const int NC = 16;
    for (int c = 0; c < NC; c++) {
        int cur = c & 1;
        cp_wait0();
        __syncthreads();
        if (c + 1 < NC) {
            int k0 = (c + 1) * 128;
            uint32_t sb = sbase + ((c + 1) & 1) * S_STAGE;
#pragma unroll
            for (int i = 0; i < 2; i++) {
                uint32_t d = sb + soA[i];
                cp16(d, pA[i] + k0); cp16(d + S_AB, pA[i] + k0 + 64);
            }
#pragma unroll
            for (int i = 0; i < 4; i++) {
                uint32_t d = sb + 2 * S_AB + soB[i];
                cp16(d, pB[i] + k0); cp16(d + S_BB, pB[i] + k0 + 64);
            }
            cp_commit();
        }
        mma_stage_b(sbase + cur * S_STAGE, wm, wn, lane, C);
        __syncthreads();
    }

#pragma unroll
    for (int i = 0; i < 2; i++)
#pragma unroll
        for (int j = 0; j < 8; j++) {
            int r0 = m0 + wm + i * 16 + (lane >> 2);
            int col = e0 + wn + j * 8 + (lane & 3) * 2;
            *(float2*)&g_xs[(size_t)r0 * DIM + col] =
                make_float2(C[i][j][0], C[i][j][1]);
            *(float2*)&g_xs[(size_t)(r0 + 8) * DIM + col] =
                make_float2(C[i][j][2], C[i][j][3]);
        }
}

// ---------------------------------------------------------------------------
// blend + layernorm -> paired hi/lo xn
// ---------------------------------------------------------------------------
__inline__ __device__ float warp_sum(float v) {
#pragma unroll
    for (int o = 16; o > 0; o >>= 1) v += __shfl_xor_sync(0xffffffffu, v, o);
    return v;
}

union U4 { uint2 u; __nv_bfloat16 b[4]; };

__global__ __launch_bounds__(256)
void k_ln(const float* __restrict__ x, const float* __restrict__ sg,
          const float* __restrict__ lnw, const float* __restrict__ lnb)
{
    int m = blockIdx.x;
    int tid = threadIdx.x;
    const float4* row = (const float4*)(g_xs + (size_t)m * DIM);
    float4 v  = row[tid];
    float4 xv = ((const float4*)(x + (size_t)m * DIM))[tid];
    float4 gv = ((const float4*)sg)[tid];
    float g0 = 1.f/(1.f+expf(-gv.x)), g1 = 1.f/(1.f+expf(-gv.y));
    float g2 = 1.f/(1.f+expf(-gv.z)), g3 = 1.f/(1.f+expf(-gv.w));
    v.x = v.x*g0 + xv.x*(1.f-g0);
    v.y = v.y*g1 + xv.y*(1.f-g1);
    v.z = v.z*g2 + xv.z*(1.f-g2);
    v.w = v.w*g3 + xv.w*(1.f-g3);

    float s  = v.x + v.y + v.z + v.w;
    float ss = fmaf(v.x, v.x, fmaf(v.y, v.y, fmaf(v.z, v.z, v.w * v.w)));
    s = warp_sum(s); ss = warp_sum(ss);
    __shared__ float sh_s[8], sh_ss[8];
    int wid = tid >> 5, lane = tid & 31;
    if (lane == 0) { sh_s[wid] = s; sh_ss[wid] = ss; }
    __syncthreads();
    if (wid == 0) {
        float a = (lane < 8) ? sh_s[lane] : 0.f;
        float b = (lane < 8) ? sh_ss[lane] : 0.f;
        a = warp_sum(a); b = warp_sum(b);
        if (lane == 0) { sh_s[0] = a; sh_ss[0] = b; }
    }
    __syncthreads();
    float mu  = sh_s[0] * (1.f / DIM);
    float var = sh_ss[0] * (1.f / DIM) - mu * mu;
    float rstd = rsqrtf(var + 1e-5f);
    float4 w4 = ((const float4*)lnw)[tid];
    float4 b4 = ((const float4*)lnb)[tid];
    float f[4];
    f[0] = (v.x - mu) * rstd * w4.x + b4.x;
    f[1] = (v.y - mu) * rstd * w4.y + b4.y;
    f[2] = (v.z - mu) * rstd * w4.z + b4.z;
    f[3] = (v.w - mu) * rstd * w4.w + b4.w;
    U4 H, L;
#pragma unroll
    for (int j = 0; j < 4; j++) {
        __nv_bfloat16 h = __float2bfloat16(f[j]);
        H.b[j] = h;
        L.b[j] = __float2bfloat16(f[j] - __bfloat162float(h));
    }
    int col = tid * 4;
    size_t dst = (size_t)m * 2048 + (col >> 6) * 128 + (col & 63);
    *(uint2*)(g_xn2 + dst)      = H.u;
    *(uint2*)(g_xn2 + dst + 64) = L.u;
}

// ---------------------------------------------------------------------------
// GEMM 2: [k|v] interleaved = xn @ Wkv^T, fused wkv epilogue (3-stage, 256 thr)
// ---------------------------------------------------------------------------
__global__ __launch_bounds__(256)
void k_gemm_kv(const float* __restrict__ time_first)
{
    extern __shared__ __align__(128) char smc[];
    const uint32_t sbase = smem_u32(smc);
    const int tid = threadIdx.x;
    const int warp = tid >> 5, lane = tid & 31;
    const int wm = (warp & 1) * 64, wn = (warp >> 1) * 32;
    const int m0 = blockIdx.y * 128;

    const int grp = tid & 7;
    const __nv_bfloat16 *pA[4], *pB[4];
    uint32_t soff[4];
#pragma unroll
    for (int i = 0; i < 4; i++) {
        int r = (tid >> 3) + i * 32;
        pA[i] = g_xn2 + (size_t)(m0 + r) * 2048 + grp * 8;
        pB[i] = g_Wkv2 + (size_t)r * 2048 + grp * 8;
        soff[i] = r * 128 + ((grp ^ (r & 7)) << 4);
    }

    float C[4][4][4];
#pragma unroll
    for (int i = 0; i < 4; i++)
#pragma unroll
        for (int j = 0; j < 4; j++)
#pragma unroll
            for (int q = 0; q < 4; q++) C[i][j][q] = 0.f;

#pragma unroll
    for (int pc = 0; pc < 2; pc++) {
        uint32_t sb = sbase + pc * STAGE;
        int k0 = pc * 128;
#pragma unroll
        for (int i = 0; i < 4; i++) {
            uint32_t d = sb + soff[i];
            cp16(d,              pA[i] + k0); cp16(d + TILE_B,     pA[i] + k0 + 64);
            cp16(d + 2 * TILE_B, pB[i] + k0); cp16(d + 3 * TILE_B, pB[i] + k0 + 64);
        }
        cp_commit();
    }

    const int NC = 16;
    int buf = 0;
    for (int c = 0; c < NC; c++) {
        if (c == NC - 1) cp_wait0(); else cp_wait1();
        __syncthreads();
        if (c + 2 < NC) {
            int k0 = (c + 2) * 128;
            int nb = buf + 2; if (nb >= NSTAGE) nb -= NSTAGE;
            uint32_t sb = sbase + nb * STAGE;
#pragma unroll
            for (int i = 0; i < 4; i++) {
                uint32_t d = sb + soff[i];
                cp16(d,              pA[i] + k0); cp16(d + TILE_B,     pA[i] + k0 + 64);
                cp16(d + 2 * TILE_B, pB[i] + k0); cp16(d + 3 * TILE_B, pB[i] + k0 + 64);
            }
            cp_commit();
        }
        mma_stage(sbase + buf * STAGE, wm, wn, lane, C);
        __syncthreads();
        if (++buf == NSTAGE) buf = 0;
    }

    // C cols: even = k_s, odd = v_s
#pragma unroll
    for (int i = 0; i < 4; i++)
#pragma unroll
        for (int j = 0; j < 4; j++) {
            int r0 = m0 + wm + i * 16 + (lane >> 2);
            int sidx = (wn >> 1) + j * 4 + (lane & 3);
            float ex = expf(time_first[sidx]);
            float k0v = C[i][j][0], v0v = C[i][j][1];
            float k1v = C[i][j][2], v1v = C[i][j][3];
            float w0 = expf(-ex * (1.f / (1.f + expf(-k0v)))) * v0v;
            float w1 = expf(-ex * (1.f / (1.f + expf(-k1v)))) * v1v;
            g_wkv[(size_t)r0 * SDIM + sidx]       = w0;
            g_wkv[(size_t)(r0 + 8) * SDIM + sidx] = w1;
        }
}

// ---------------------------------------------------------------------------
// Recurrence (chunked scan, CH=128)
// ---------------------------------------------------------------------------
__global__ void k_rec_lasts(const float* __restrict__ td)
{
    int ch = blockIdx.x, b = blockIdx.y, s = threadIdx.x;
    float w = expf(td[s]);
    const float* wp = g_wkv + ((size_t)(b * SEQ + ch * CH)) * SDIM + s;
    float st = 0.f;
#pragma unroll 8
    for (int t = 0; t < CH; t++) st = fmaf(st, w, wp[(size_t)t * SDIM]);
    g_lasts[(b * NCH + ch) * SDIM + s] = st;
}

__global__ void k_rec_carry(const float* __restrict__ td, float* __restrict__ last_out)
{
    int b = blockIdx.x, s = threadIdx.x;
    float wC = expf((float)CH * td[s]);
    float st = 0.f;
    for (int c = 0; c < NCH; c++) {
        g_carry[(b * NCH + c) * SDIM + s] = st;
        st = st * wC + g_lasts[(b * NCH + c) * SDIM + s];
    }
    last_out[b * SDIM + s] = st;
}

__global__ void k_rec_scan(const float* __restrict__ td)
{
    int ch = blockIdx.x, b = blockIdx.y, s = threadIdx.x;
    float w = expf(td[s]);
    float st = g_carry[(b * NCH + ch) * SDIM + s];
    size_t m0 = (size_t)(b * SEQ + ch * CH);
    const float* wp = g_wkv + m0 * SDIM + s;
#pragma unroll 8
    for (int t = 0; t < CH; t++) {
        st = fmaf(st, w, wp[(size_t)t * SDIM]);
        __nv_bfloat16 h = __float2bfloat16(st);
        size_t dst = (m0 + t) * 128 + s;
        g_st2[dst]      = h;
        g_st2[dst + 64] = __float2bfloat16(st - __bfloat162float(h));
    }
}

// ---------------------------------------------------------------------------
// GEMM 3: out = states @ Wo^T  (K = 64, single chunk, 256 thr)
// ---------------------------------------------------------------------------
__global__ __launch_bounds__(256)
void k_gemm_out(float* __restrict__ out)
{
    extern __shared__ __align__(128) char smc[];
    const uint32_t sbase = smem_u32(smc);
    const int tid = threadIdx.x;
    const int warp = tid >> 5, lane = tid & 31;
    const int wm = (warp & 1) * 64, wn = (warp >> 1) * 32;
    const int m0 = blockIdx.y * 128, d0 = blockIdx.x * 128;

    const int grp = tid & 7;
#pragma unroll
    for (int i = 0; i < 4; i++) {
        int r = (tid >> 3) + i * 32;
        uint32_t so = r * 128 + ((grp ^ (r & 7)) << 4);
        uint32_t d = sbase + so;
        const __nv_bfloat16* pa = g_st2 + (size_t)(m0 + r) * 128 + grp * 8;
        const __nv_bfloat16* pb = g_Wo2 + (size_t)(d0 + r) * 128 + grp * 8;
        cp16(d,              pa); cp16(d + TILE_B,     pa + 64);
        cp16(d + 2 * TILE_B, pb); cp16(d + 3 * TILE_B, pb + 64);
    }
    cp_commit();

    float C[4][4][4];
#pragma unroll
    for (int i = 0; i < 4; i++)
#pragma unroll
        for (int j = 0; j < 4; j++)
#pragma unroll
            for (int q = 0; q < 4; q++) C[i][j][q] = 0.f;

    cp_wait0();
    __syncthreads();
    mma_stage(sbase, wm, wn, lane, C);

#pragma unroll
    for (int i = 0; i < 4; i++)
#pragma unroll
        for (int j = 0; j < 4; j++) {
            int r0 = m0 + wm + i * 16 + (lane >> 2);
            int col = d0 + wn + j * 8 + (lane & 3) * 2;
            *(float2*)&out[(size_t)r0 * DIM + col] =
                make_float2(C[i][j][0], C[i][j][1]);
            *(float2*)&out[(size_t)(r0 + 8) * DIM + col] =
                make_float2(C[i][j][2], C[i][j][3]);
        }
}

// ---------------------------------------------------------------------------
extern "C" void kernel_launch(void* const* d_in, const int* in_sizes, int n_in,
                              void* d_out, int out_size)
{
    const float* x   = (const float*)d_in[0];
    const float* td  = (const float*)d_in[1];
    const float* tf  = (const float*)d_in[2];
    const float* Wk  = (const float*)d_in[3];
    const float* Wv  = (const float*)d_in[4];
    const float* Wo  = (const float*)d_in[5];
    const float* Wsh = (const float*)d_in[6];
    const float* sg  = (const float*)d_in[7];
    const float* lnw = (const float*)d_in[8];
    const float* lnb = (const float*)d_in[9];

    float* out  = (float*)d_out;
    float* last = out + (size_t)MTOT * DIM;

    const int SMEM_S = 2 * S_STAGE;     // 196608
    const int SMEM3  = NSTAGE * STAGE;  // 196608
    const int SMEM1  = STAGE;           // 65536
    cudaFuncSetAttribute(k_gemm_shift, cudaFuncAttributeMaxDynamicSharedMemorySize, SMEM_S);
    cudaFuncSetAttribute(k_gemm_kv,    cudaFuncAttributeMaxDynamicSharedMemorySize, SMEM3);
    cudaFuncSetAttribute(k_gemm_out,   cudaFuncAttributeMaxDynamicSharedMemorySize, SMEM1);

    // launch index 3 = k_gemm_shift -> profiled by ncu
    k_prep_x  <<<16384, 256>>>(x);
    k_prep_wsh<<<512,   256>>>(Wsh);
    k_prep_wkv<<<64,    256>>>(Wk, Wv);
    k_gemm_shift<<<dim3(DIM / S_TN, MTOT / S_TM), 512, SMEM_S>>>();

    k_prep_wo <<<32,    256>>>(Wo);
    k_ln<<<MTOT, 256>>>(x, sg, lnw, lnb);
    k_gemm_kv<<<dim3(1, MTOT / 128), 256, SMEM3>>>(tf);

    k_rec_lasts<<<dim3(NCH, BATCH), SDIM>>>(td);
    k_rec_carry<<<BATCH, SDIM>>>(td, last);
    k_rec_scan <<<dim3(NCH, BATCH), SDIM>>>(td);

    k_gemm_out<<<dim3(DIM / 128, MTOT / 128), 256, SMEM1>>>(out);
}